// round 1
// baseline (speedup 1.0000x reference)
#include <cuda_runtime.h>
#include <math.h>

// ---------------- problem constants ----------------
#define BB   16          // batch
#define CC   64          // EEG channels (conv "height")
#define WW   125000      // samples
#define TT   99          // conv output time steps
#define SS   100         // 1250-sample segments per row (TT+1)
#define RR   66          // padded rows (CC + 2, replicate)
#define KK   1250        // GEMM K (segment length)
#define KPAD 1280        // K padded to multiple of BK (zeros in weights)
#define NN   192         // GEMM N = 32 oc * 3 kh * 2 halves
#define OCC  32

// ---------------- scratch (device globals: no allocs allowed) ----------------
__device__ float g_Wp[KPAD * NN];                       // packed weights, k-major [k][n]
__device__ float g_D[(size_t)BB * RR * SS * NN];        // segment-GEMM output, 81 MB
__device__ float g_z[BB * CC * TT];                     // fused conv2 output

// ---------------- kernel 0: pack weights ----------------
// n = (kh*2 + h)*32 + oc ;  Wp[k][n] = conv_w[oc][0][kh][h*1250 + k], zero for k>=1250
__global__ void pack_w_kernel(const float* __restrict__ conv_w) {
    int i = blockIdx.x * blockDim.x + threadIdx.x;
    if (i >= KPAD * NN) return;
    int k = i / NN;
    int n = i - k * NN;
    int grp = n >> 5;            // 0..5
    int oc  = n & 31;
    int kh  = grp >> 1;
    int h   = grp & 1;
    float v = 0.0f;
    if (k < KK) v = conv_w[(oc * 3 + kh) * 2500 + h * 1250 + k];
    g_Wp[k * NN + n] = v;
}

// ---------------- kernel 1: segment GEMM (fp32 SGEMM) ----------------
// D[m][n] = sum_k A[m][k] * Wp[k][n]
// A row m=(b,r,s) is contiguous: x + (b*64 + clamp(r-1,0,63))*125000 + s*1250
#define BM 64
#define BN 64
#define BK 16

__global__ __launch_bounds__(128) void seg_gemm_kernel(const float* __restrict__ x) {
    __shared__ __align__(16) float As[BK][BM];
    __shared__ __align__(16) float Bs[BK][BN];

    const int tid = threadIdx.x;
    const int m0  = blockIdx.x * BM;
    const int n0  = blockIdx.y * BN;

    // ---- A global-load mapping: thread -> (row ar, k-half akh), 8 floats via 4x float2
    const int ar  = tid >> 1;        // 0..63
    const int akh = tid & 1;         // 0..1  (k offset akh*8)
    {
        // nothing
    }
    const int m   = m0 + ar;
    const int b   = m / (RR * SS);
    const int rem = m - b * (RR * SS);
    const int r   = rem / SS;
    const int s   = rem - r * SS;
    int c = r - 1; c = c < 0 ? 0 : (c > 63 ? 63 : c);
    const float* __restrict__ arow = x + ((size_t)(b * CC + c)) * WW + (size_t)s * KK;

    // ---- B global-load mapping: thread -> (k-row bk, 8 cols at bn)
    const int bk = tid >> 3;         // 0..15
    const int bn = (tid & 7) * 8;    // 0..56

    // ---- compute mapping: thread -> 8 rows (rty*8) x 4 cols (ctx*4)
    const int rty = tid >> 4;        // 0..7
    const int ctx = tid & 15;        // 0..15

    float acc[8][4];
#pragma unroll
    for (int i = 0; i < 8; i++)
#pragma unroll
        for (int j = 0; j < 4; j++) acc[i][j] = 0.0f;

    float2 a_reg[4];
    float4 b_reg[2];

    // prologue: load tile kt=0
    {
        const int kt = 0;
#pragma unroll
        for (int i = 0; i < 4; i++) {
            int kg = kt * BK + akh * 8 + 2 * i;
            if (kg < KK) a_reg[i] = *reinterpret_cast<const float2*>(arow + kg);
            else         a_reg[i] = make_float2(0.0f, 0.0f);
        }
        const float* p = g_Wp + (size_t)(kt * BK + bk) * NN + n0 + bn;
        b_reg[0] = *reinterpret_cast<const float4*>(p);
        b_reg[1] = *reinterpret_cast<const float4*>(p + 4);
    }

    const int NKT = KPAD / BK;   // 80
    for (int kt = 0; kt < NKT; kt++) {
        __syncthreads();
        // store current tile to SMEM (A transposed)
#pragma unroll
        for (int i = 0; i < 4; i++) {
            As[akh * 8 + 2 * i + 0][ar] = a_reg[i].x;
            As[akh * 8 + 2 * i + 1][ar] = a_reg[i].y;
        }
        *reinterpret_cast<float4*>(&Bs[bk][bn])     = b_reg[0];
        *reinterpret_cast<float4*>(&Bs[bk][bn + 4]) = b_reg[1];
        __syncthreads();

        // prefetch next tile into registers (overlaps with FMAs below)
        const int ktn = (kt + 1 < NKT) ? (kt + 1) : kt;
#pragma unroll
        for (int i = 0; i < 4; i++) {
            int kg = ktn * BK + akh * 8 + 2 * i;
            if (kg < KK) a_reg[i] = *reinterpret_cast<const float2*>(arow + kg);
            else         a_reg[i] = make_float2(0.0f, 0.0f);
        }
        {
            const float* p = g_Wp + (size_t)(ktn * BK + bk) * NN + n0 + bn;
            b_reg[0] = *reinterpret_cast<const float4*>(p);
            b_reg[1] = *reinterpret_cast<const float4*>(p + 4);
        }

        // compute
#pragma unroll
        for (int k = 0; k < BK; k++) {
            float4 a0 = *reinterpret_cast<const float4*>(&As[k][rty * 8 + 0]);
            float4 a1 = *reinterpret_cast<const float4*>(&As[k][rty * 8 + 4]);
            float4 bb = *reinterpret_cast<const float4*>(&Bs[k][ctx * 4]);
            float av[8] = {a0.x, a0.y, a0.z, a0.w, a1.x, a1.y, a1.z, a1.w};
            float bv[4] = {bb.x, bb.y, bb.z, bb.w};
#pragma unroll
            for (int i = 0; i < 8; i++)
#pragma unroll
                for (int j = 0; j < 4; j++)
                    acc[i][j] = fmaf(av[i], bv[j], acc[i][j]);
        }
    }

    // write D
#pragma unroll
    for (int i = 0; i < 8; i++) {
        float4 v = make_float4(acc[i][0], acc[i][1], acc[i][2], acc[i][3]);
        *reinterpret_cast<float4*>(g_D + (size_t)(m0 + rty * 8 + i) * NN + n0 + ctx * 4) = v;
    }
}

// ---------------- kernel 2: combine + bias + relu + 1x1 conv + relu ----------------
// One warp per (b,c,t); lane = oc.
__global__ void epilogue_kernel(const float* __restrict__ conv_b,
                                const float* __restrict__ conv2_w,
                                const float* __restrict__ conv2_b) {
    int gw   = (blockIdx.x * blockDim.x + threadIdx.x) >> 5;
    int lane = threadIdx.x & 31;
    if (gw >= BB * CC * TT) return;
    int b   = gw / (CC * TT);
    int rem = gw - b * (CC * TT);
    int c   = rem / TT;
    int t   = rem - c * TT;

    float sum = 0.0f;
#pragma unroll
    for (int kh = 0; kh < 3; kh++) {
#pragma unroll
        for (int h = 0; h < 2; h++) {
            size_t row = ((size_t)(b * RR + (c + kh)) * SS + (t + h));
            sum += g_D[row * NN + (kh * 2 + h) * 32 + lane];
        }
    }
    float y = fmaxf(sum + conv_b[lane], 0.0f);
    float v = y * conv2_w[lane];
#pragma unroll
    for (int o = 16; o > 0; o >>= 1)
        v += __shfl_xor_sync(0xffffffffu, v, o);
    if (lane == 0) {
        float z = fmaxf(v + conv2_b[0], 0.0f);
        g_z[(b * CC + c) * TT + t] = z;
    }
}

// ---------------- kernel 3: scalar Elman RNN scan + sigmoid ----------------
__global__ void rnn_kernel(const float* __restrict__ w_ih,
                           const float* __restrict__ w_hh,
                           const float* __restrict__ b_ih,
                           const float* __restrict__ b_hh,
                           const float* __restrict__ h0,
                           float* __restrict__ out) {
    int i = blockIdx.x * blockDim.x + threadIdx.x;
    if (i >= BB * CC) return;
    int b = i / CC;
    float wih  = w_ih[0];
    float whh  = w_hh[0];
    float bias = b_ih[0] + b_hh[0];
    float h = h0[b];
    const float* __restrict__ zp = g_z + (size_t)i * TT;
#pragma unroll 1
    for (int t = 0; t < TT; t++) {
        h = tanhf(fmaf(wih, zp[t], fmaf(whh, h, bias)));
    }
    out[i] = 1.0f / (1.0f + expf(-h));
}

// ---------------- launcher ----------------
extern "C" void kernel_launch(void* const* d_in, const int* in_sizes, int n_in,
                              void* d_out, int out_size) {
    const float* x       = (const float*)d_in[0];
    const float* conv_w  = (const float*)d_in[1];
    const float* conv_b  = (const float*)d_in[2];
    const float* conv2_w = (const float*)d_in[3];
    const float* conv2_b = (const float*)d_in[4];
    const float* w_ih    = (const float*)d_in[5];
    const float* w_hh    = (const float*)d_in[6];
    const float* b_ih    = (const float*)d_in[7];
    const float* b_hh    = (const float*)d_in[8];
    const float* h0      = (const float*)d_in[9];
    float* out = (float*)d_out;

    // 0) pack weights (k-major, zero-padded K)
    pack_w_kernel<<<(KPAD * NN + 255) / 256, 256>>>(conv_w);

    // 1) segment GEMM: M=105600, N=192, K=1250
    dim3 grid((BB * RR * SS) / BM, NN / BN);   // (1650, 3)
    seg_gemm_kernel<<<grid, 128>>>(x);

    // 2) epilogue: one warp per (b,c,t)
    int total_warps = BB * CC * TT;            // 101376
    epilogue_kernel<<<(total_warps * 32 + 255) / 256, 256>>>(conv_b, conv2_w, conv2_b);

    // 3) RNN scan + sigmoid
    rnn_kernel<<<(BB * CC + 127) / 128, 128>>>(w_ih, w_hh, b_ih, b_hh, h0, out);
}

// round 3
// speedup vs baseline: 3.7775x; 3.7775x over previous
#include <cuda_runtime.h>
#include <cuda_bf16.h>
#include <cstdint>
#include <math.h>

// ---------------- problem constants ----------------
#define BB   16
#define CC   64
#define WW   125000
#define TT   99
#define SS   100
#define RR   66          // padded rows
#define KK   1250        // GEMM K
#define NN   192         // 32 oc * 3 kh * 2 halves
#define NST  40          // K stages of 32
#define MTILE 128

// ---------------- scratch ----------------
__device__ float g_D[(size_t)BB * RR * SS * NN];     // 81 MB GEMM output
__device__ float g_z[BB * CC * TT];
// packed weights bf16: [stage c][p=hi/lo][n=192][k=32]
__device__ __align__(16) __nv_bfloat16 g_B[NST * 2 * NN * 32];

// ---------------- helpers ----------------
__device__ __forceinline__ uint32_t smem_u32(const void* p) {
    uint32_t a;
    asm("{ .reg .u64 t; cvta.to.shared.u64 t, %1; cvt.u32.u64 %0, t; }" : "=r"(a) : "l"(p));
    return a;
}
#define LDSM4(r0,r1,r2,r3, addr) \
    asm volatile("ldmatrix.sync.aligned.m8n8.x4.shared.b16 {%0,%1,%2,%3}, [%4];" \
        : "=r"(r0),"=r"(r1),"=r"(r2),"=r"(r3) : "r"(addr))
#define CPASYNC16(dst, src) \
    asm volatile("cp.async.cg.shared.global [%0], [%1], 16;" :: "r"(dst), "l"(src))
#define CPCOMMIT() asm volatile("cp.async.commit_group;" ::: "memory")
#define CPWAIT0()  asm volatile("cp.async.wait_group 0;" ::: "memory")

__device__ __forceinline__ void mma16816(float* c, const uint32_t* a, const uint32_t* b) {
    asm volatile("mma.sync.aligned.m16n8k16.row.col.f32.bf16.bf16.f32 "
        "{%0,%1,%2,%3}, {%4,%5,%6,%7}, {%8,%9}, {%0,%1,%2,%3};"
        : "+f"(c[0]), "+f"(c[1]), "+f"(c[2]), "+f"(c[3])
        : "r"(a[0]), "r"(a[1]), "r"(a[2]), "r"(a[3]), "r"(b[0]), "r"(b[1]));
}

// ---------------- SMEM layout (dynamic) ----------------
// per buffer (51200 B): A_hi [0,10240) 128 rows x 80B; A_lo [10240,20480);
//                       B hi+lo [20480,51200) 384 rows x 80B
#define BUFSZ   51200
#define OFF_AL  10240
#define OFF_B   20480
#define SMEM_BYTES (2 * BUFSZ)

// ---------------- kernel 0: pack weights -> bf16 hi/lo ----------------
__global__ void pack_w_kernel(const float* __restrict__ conv_w) {
    int i = blockIdx.x * blockDim.x + threadIdx.x;
    if (i >= NST * NN * 32) return;
    int c = i / (NN * 32);
    int r = i - c * (NN * 32);
    int n = r >> 5;
    int k = r & 31;
    int kk = c * 32 + k;
    int grp = n >> 5;          // 0..5
    int oc  = n & 31;
    int kh  = grp >> 1;
    int h   = grp & 1;
    float w = 0.0f;
    if (kk < KK) w = conv_w[oc * 7500 + kh * 2500 + h * 1250 + kk];
    __nv_bfloat16 hi = __float2bfloat16_rn(w);
    float res = w - __bfloat162float(hi);
    g_B[((size_t)c * 384 + n) * 32 + k]       = hi;
    g_B[((size_t)c * 384 + 192 + n) * 32 + k] = __float2bfloat16_rn(res);
}

// ---------------- kernel 1: HMMA segment GEMM (bf16 3-pass) ----------------
__global__ __launch_bounds__(256, 1) void seg_gemm_mma(const float* __restrict__ x) {
    extern __shared__ char smem[];
    const uint32_t sb = smem_u32(smem);
    const int tid  = threadIdx.x;
    const int wid  = tid >> 5;
    const int lane = tid & 31;

    // ---- A global source: row r = tid>>1 (0..127), half = tid&1 (k offset 16) ----
    const int r    = tid >> 1;
    const int half = tid & 1;
    const float* asrc;
    {
        int m = blockIdx.x * MTILE + r;
        int b = m / (RR * SS);
        int rem = m - b * (RR * SS);
        int rr = rem / SS;
        int s  = rem - rr * SS;
        int ch = rr - 1; ch = ch < 0 ? 0 : (ch > 63 ? 63 : ch);
        asrc = x + ((size_t)(b * CC + ch)) * WW + (size_t)s * KK + half * 16;
    }

    // ---- warp tiling: warpM = (wid&3)*32, warpN = (wid>>2)*96 ----
    const int warpM = (wid & 3) * 32;
    const int warpN = (wid >> 2) * 96;
    // ldmatrix lane-address invariants (80B row stride)
    const uint32_t invA = (uint32_t)((warpM + (lane & 15)) * 80 + ((lane >> 4) * 16));
    const uint32_t invB = (uint32_t)((warpN + (lane & 7) + ((lane & 16) >> 1)) * 80 + ((lane & 8) << 1));

    float acc[2][12][4];
#pragma unroll
    for (int i = 0; i < 2; i++)
#pragma unroll
        for (int j = 0; j < 12; j++)
#pragma unroll
            for (int q = 0; q < 4; q++) acc[i][j][q] = 0.0f;

    float2 f2[8];

    // stage A load into registers (16 floats, zero past K)
    auto loadA = [&](int c) {
#pragma unroll
        for (int q = 0; q < 8; q++) {
            int kk = c * 32 + half * 16 + 2 * q;
            if (kk < KK) f2[q] = *reinterpret_cast<const float2*>(asrc + c * 32 + 2 * q);
            else         f2[q] = make_float2(0.0f, 0.0f);
        }
    };
    // split + STS into buffer
    auto stsA = [&](int buf) {
        uint32_t uh[8], ul[8];
#pragma unroll
        for (int q = 0; q < 8; q++) {
            float a0 = f2[q].x, a1 = f2[q].y;
            __nv_bfloat162 hp = __floats2bfloat162_rn(a0, a1);
            float r0 = a0 - __low2float(hp);
            float r1 = a1 - __high2float(hp);
            __nv_bfloat162 lp = __floats2bfloat162_rn(r0, r1);
            uh[q] = *reinterpret_cast<uint32_t*>(&hp);
            ul[q] = *reinterpret_cast<uint32_t*>(&lp);
        }
        uint32_t base = sb + buf * BUFSZ + r * 80 + half * 32;
        asm volatile("st.shared.v4.b32 [%0], {%1,%2,%3,%4};" :: "r"(base),      "r"(uh[0]), "r"(uh[1]), "r"(uh[2]), "r"(uh[3]) : "memory");
        asm volatile("st.shared.v4.b32 [%0], {%1,%2,%3,%4};" :: "r"(base + 16), "r"(uh[4]), "r"(uh[5]), "r"(uh[6]), "r"(uh[7]) : "memory");
        asm volatile("st.shared.v4.b32 [%0], {%1,%2,%3,%4};" :: "r"(base + OFF_AL),      "r"(ul[0]), "r"(ul[1]), "r"(ul[2]), "r"(ul[3]) : "memory");
        asm volatile("st.shared.v4.b32 [%0], {%1,%2,%3,%4};" :: "r"(base + OFF_AL + 16), "r"(ul[4]), "r"(ul[5]), "r"(ul[6]), "r"(ul[7]) : "memory");
    };
    // B: 384 rows x 64B -> 1536 16B chunks via cp.async
    auto loadB = [&](int c, int buf) {
#pragma unroll
        for (int i = 0; i < 6; i++) {
            int u = tid + 256 * i;
            int rowb = u >> 2, j = u & 3;
            uint32_t dst = sb + buf * BUFSZ + OFF_B + rowb * 80 + j * 16;
            const char* src = reinterpret_cast<const char*>(g_B) + ((size_t)c * 384 + rowb) * 64 + j * 16;
            CPASYNC16(dst, src);
        }
    };

    auto compute = [&](int buf) {
        const uint32_t ab = sb + buf * BUFSZ;
#pragma unroll
        for (int g = 0; g < 2; g++) {
            uint32_t ah[8], al[8];
            LDSM4(ah[0], ah[1], ah[2], ah[3], ab + invA + g * 32);
            LDSM4(ah[4], ah[5], ah[6], ah[7], ab + invA + 16 * 80 + g * 32);
            LDSM4(al[0], al[1], al[2], al[3], ab + OFF_AL + invA + g * 32);
            LDSM4(al[4], al[5], al[6], al[7], ab + OFF_AL + invA + 16 * 80 + g * 32);
#pragma unroll
            for (int ng = 0; ng < 6; ng++) {
                uint32_t bh[4], bl[4];
                LDSM4(bh[0], bh[1], bh[2], bh[3], ab + OFF_B + invB + ng * 1280 + g * 32);
                LDSM4(bl[0], bl[1], bl[2], bl[3], ab + OFF_B + 192 * 80 + invB + ng * 1280 + g * 32);
#pragma unroll
                for (int mt = 0; mt < 2; mt++) {
#pragma unroll
                    for (int nh = 0; nh < 2; nh++) {
                        float* cc = acc[mt][ng * 2 + nh];
                        mma16816(cc, ah + mt * 4, bh + nh * 2);   // hi*hi
                        mma16816(cc, ah + mt * 4, bl + nh * 2);   // hi*lo
                        mma16816(cc, al + mt * 4, bh + nh * 2);   // lo*hi
                    }
                }
            }
        }
    };

    // ---- prologue ----
    loadA(0);
    loadB(0, 0);
    CPCOMMIT();
    stsA(0);
    CPWAIT0();
    __syncthreads();

    // ---- main loop ----
    for (int c = 0; c < NST; c++) {
        const int buf = c & 1;
        if (c < NST - 1) { loadA(c + 1); loadB(c + 1, buf ^ 1); CPCOMMIT(); }
        compute(buf);
        if (c < NST - 1) { stsA(buf ^ 1); CPWAIT0(); }
        __syncthreads();
    }

    // ---- write D ----
    const int l4 = lane >> 2;
    const int l2 = (lane & 3) * 2;
#pragma unroll
    for (int mt = 0; mt < 2; mt++) {
        const int mrow = blockIdx.x * MTILE + warpM + mt * 16 + l4;
        float* dbase = g_D + (size_t)mrow * NN + warpN + l2;
#pragma unroll
        for (int nt = 0; nt < 12; nt++) {
            *reinterpret_cast<float2*>(dbase + nt * 8)            = make_float2(acc[mt][nt][0], acc[mt][nt][1]);
            *reinterpret_cast<float2*>(dbase + nt * 8 + 8 * NN)   = make_float2(acc[mt][nt][2], acc[mt][nt][3]);
        }
    }
}

// ---------------- kernel 2: combine + bias + relu + 1x1 conv + relu ----------------
__global__ void epilogue_kernel(const float* __restrict__ conv_b,
                                const float* __restrict__ conv2_w,
                                const float* __restrict__ conv2_b) {
    int gw   = (blockIdx.x * blockDim.x + threadIdx.x) >> 5;
    int lane = threadIdx.x & 31;
    if (gw >= BB * CC * TT) return;
    int b   = gw / (CC * TT);
    int rem = gw - b * (CC * TT);
    int c   = rem / TT;
    int t   = rem - c * TT;

    float sum = 0.0f;
#pragma unroll
    for (int kh = 0; kh < 3; kh++) {
#pragma unroll
        for (int h = 0; h < 2; h++) {
            size_t row = ((size_t)(b * RR + (c + kh)) * SS + (t + h));
            sum += g_D[row * NN + (kh * 2 + h) * 32 + lane];
        }
    }
    float y = fmaxf(sum + conv_b[lane], 0.0f);
    float v = y * conv2_w[lane];
#pragma unroll
    for (int o = 16; o > 0; o >>= 1)
        v += __shfl_xor_sync(0xffffffffu, v, o);
    if (lane == 0) {
        g_z[(b * CC + c) * TT + t] = fmaxf(v + conv2_b[0], 0.0f);
    }
}

// ---------------- kernel 3: RNN scan + sigmoid (fast tanh) ----------------
__global__ void rnn_kernel(const float* __restrict__ w_ih,
                           const float* __restrict__ w_hh,
                           const float* __restrict__ b_ih,
                           const float* __restrict__ b_hh,
                           const float* __restrict__ h0,
                           float* __restrict__ out) {
    int i = blockIdx.x * blockDim.x + threadIdx.x;
    if (i >= BB * CC) return;
    int b = i / CC;
    float wih  = w_ih[0];
    float whh  = w_hh[0];
    float bias = b_ih[0] + b_hh[0];
    float h = h0[b];
    const float* __restrict__ zp = g_z + (size_t)i * TT;
#pragma unroll 1
    for (int t = 0; t < TT; t++) {
        float a = fmaf(wih, zp[t], fmaf(whh, h, bias));
        float e = __expf(2.0f * a);
        h = 1.0f - __fdividef(2.0f, e + 1.0f);   // tanh(a)
    }
    out[i] = __fdividef(1.0f, 1.0f + __expf(-h));
}

// ---------------- launcher ----------------
extern "C" void kernel_launch(void* const* d_in, const int* in_sizes, int n_in,
                              void* d_out, int out_size) {
    const float* x       = (const float*)d_in[0];
    const float* conv_w  = (const float*)d_in[1];
    const float* conv_b  = (const float*)d_in[2];
    const float* conv2_w = (const float*)d_in[3];
    const float* conv2_b = (const float*)d_in[4];
    const float* w_ih    = (const float*)d_in[5];
    const float* w_hh    = (const float*)d_in[6];
    const float* b_ih    = (const float*)d_in[7];
    const float* b_hh    = (const float*)d_in[8];
    const float* h0      = (const float*)d_in[9];
    float* out = (float*)d_out;

    static int smem_set = 0;
    if (!smem_set) {
        cudaFuncSetAttribute(seg_gemm_mma, cudaFuncAttributeMaxDynamicSharedMemorySize, SMEM_BYTES);
        smem_set = 1;
    }

    pack_w_kernel<<<(NST * NN * 32 + 255) / 256, 256>>>(conv_w);

    seg_gemm_mma<<<(BB * RR * SS) / MTILE, 256, SMEM_BYTES>>>(x);   // 825 CTAs

    int total_warps = BB * CC * TT;
    epilogue_kernel<<<(total_warps * 32 + 255) / 256, 256>>>(conv_b, conv2_w, conv2_b);

    rnn_kernel<<<(BB * CC + 127) / 128, 128>>>(w_ih, w_hh, b_ih, b_hh, h0, out);
}

// round 5
// speedup vs baseline: 6.2981x; 1.6673x over previous
#include <cuda_runtime.h>
#include <cuda_fp16.h>
#include <cstdint>
#include <math.h>

// ---------------- problem constants ----------------
#define BB   16
#define CC   64
#define WW   125000
#define TT   99
#define SS   100
#define RR   66          // padded rows
#define KK   1250        // GEMM K
#define NN   192         // 32 oc * 3 kh * 2 halves
#define BK   64          // K per stage
#define NST  20          // stages (last zero-padded via weights + guarded A)
#define MTILE 128

// ---------------- scratch ----------------
__device__ float g_D[(size_t)BB * RR * SS * NN];     // 81 MB GEMM output
__device__ float g_z[BB * CC * TT];
// packed weights fp16: [stage][n=192][k=64]
__device__ __align__(16) __half g_B[NST * NN * BK];

// ---------------- helpers ----------------
__device__ __forceinline__ uint32_t smem_u32(const void* p) {
    uint32_t a;
    asm("{ .reg .u64 t; cvta.to.shared.u64 t, %1; cvt.u32.u64 %0, t; }" : "=r"(a) : "l"(p));
    return a;
}
#define LDSM4(r0,r1,r2,r3, addr) \
    asm volatile("ldmatrix.sync.aligned.m8n8.x4.shared.b16 {%0,%1,%2,%3}, [%4];" \
        : "=r"(r0),"=r"(r1),"=r"(r2),"=r"(r3) : "r"(addr))
#define CPASYNC16(dst, src) \
    asm volatile("cp.async.cg.shared.global [%0], [%1], 16;" :: "r"(dst), "l"(src))
#define CPCOMMIT() asm volatile("cp.async.commit_group;" ::: "memory")
#define CPWAIT0()  asm volatile("cp.async.wait_group 0;" ::: "memory")

__device__ __forceinline__ void mma16816(float* c, const uint32_t* a, const uint32_t* b) {
    asm volatile("mma.sync.aligned.m16n8k16.row.col.f32.f16.f16.f32 "
        "{%0,%1,%2,%3}, {%4,%5,%6,%7}, {%8,%9}, {%0,%1,%2,%3};"
        : "+f"(c[0]), "+f"(c[1]), "+f"(c[2]), "+f"(c[3])
        : "r"(a[0]), "r"(a[1]), "r"(a[2]), "r"(a[3]), "r"(b[0]), "r"(b[1]));
}

// ---------------- SMEM layout (dynamic) ----------------
// row stride 144B (128B data + 16B pad) -> ldmatrix conflict-free
#define ASTRIDE 144
#define OFF_B   (128 * ASTRIDE)          // 18432
#define BUFSZ   (OFF_B + 192 * ASTRIDE)  // 46080
#define SMEM_BYTES (2 * BUFSZ)           // 92160

// ---------------- kernel 0: pack weights -> fp16, [stage][n][k64] ----------------
__global__ void pack_w_kernel(const float* __restrict__ conv_w) {
    int i = blockIdx.x * blockDim.x + threadIdx.x;
    if (i >= NST * NN * BK) return;
    int c = i / (NN * BK);
    int r = i - c * (NN * BK);
    int n = r >> 6;
    int k = r & 63;
    int kk = c * BK + k;
    int grp = n >> 5;          // 0..5
    int oc  = n & 31;
    int kh  = grp >> 1;
    int h   = grp & 1;
    float w = 0.0f;
    if (kk < KK) w = conv_w[oc * 7500 + kh * 2500 + h * 1250 + kk];
    g_B[i] = __float2half_rn(w);
}

// ---------------- kernel 1: fp16 HMMA segment GEMM (single pass) ----------------
__global__ __launch_bounds__(256, 1) void seg_gemm_mma(const float* __restrict__ x) {
    extern __shared__ char smem[];
    const uint32_t sb = smem_u32(smem);
    const int tid  = threadIdx.x;
    const int wid  = tid >> 5;
    const int lane = tid & 31;

    // ---- A global source: row = tid>>1 (0..127), qh = tid&1 (k offset 32 floats)
    // NOTE: segment bases are only 8B-aligned (1250 mod 4 = 2) -> use float2 loads.
    const int r  = tid >> 1;
    const int qh = tid & 1;
    const float* asrc;
    {
        int m = blockIdx.x * MTILE + r;
        int b = m / (RR * SS);
        int rem = m - b * (RR * SS);
        int rr = rem / SS;
        int s  = rem - rr * SS;
        int ch = rr - 1; ch = ch < 0 ? 0 : (ch > 63 ? 63 : ch);
        asrc = x + ((size_t)(b * CC + ch)) * WW + (size_t)s * KK + qh * 32;
    }

    // ---- warp tiling: warpM = (wid&3)*32, warpN = (wid>>2)*96 ----
    const int warpM = (wid & 3) * 32;
    const int warpN = (wid >> 2) * 96;
    const uint32_t invA = (uint32_t)((warpM + (lane & 15)) * ASTRIDE + ((lane >> 4) * 16));
    const uint32_t invB = (uint32_t)((warpN + (lane & 7) + ((lane & 16) >> 1)) * ASTRIDE + ((lane & 8) << 1));

    float acc[2][12][4];
#pragma unroll
    for (int i = 0; i < 2; i++)
#pragma unroll
        for (int j = 0; j < 12; j++)
#pragma unroll
            for (int q = 0; q < 4; q++) acc[i][j][q] = 0.0f;

    float2 f2[16];   // 32-float A prefetch (float2: segment base only 8B aligned)

    auto loadA = [&](int c) {
        const float* p = asrc + c * BK;
        if (c < NST - 1) {
#pragma unroll
            for (int q = 0; q < 16; q++) f2[q] = *reinterpret_cast<const float2*>(p + 2 * q);
        } else {
            const int k0 = c * BK + qh * 32;
#pragma unroll
            for (int q = 0; q < 16; q++) {
                float e0 = (k0 + 2 * q     < KK) ? p[2 * q]     : 0.0f;
                float e1 = (k0 + 2 * q + 1 < KK) ? p[2 * q + 1] : 0.0f;
                f2[q] = make_float2(e0, e1);
            }
        }
    };
    auto stsA = [&](int buf) {
        uint32_t u[16];
#pragma unroll
        for (int q = 0; q < 16; q++) {
            __half2 hh = __floats2half2_rn(f2[q].x, f2[q].y);
            u[q] = *reinterpret_cast<uint32_t*>(&hh);
        }
        uint32_t base = sb + buf * BUFSZ + r * ASTRIDE + qh * 64;
#pragma unroll
        for (int q = 0; q < 4; q++)
            asm volatile("st.shared.v4.b32 [%0], {%1,%2,%3,%4};"
                :: "r"(base + 16 * q), "r"(u[4 * q]), "r"(u[4 * q + 1]), "r"(u[4 * q + 2]), "r"(u[4 * q + 3]) : "memory");
    };
    // B: 192 rows x 128B -> 1536 16B chunks via cp.async
    auto loadB = [&](int c, int buf) {
#pragma unroll
        for (int i = 0; i < 6; i++) {
            int u = tid + 256 * i;
            int rowb = u >> 3, j = u & 7;
            uint32_t dst = sb + buf * BUFSZ + OFF_B + rowb * ASTRIDE + j * 16;
            const char* src = reinterpret_cast<const char*>(g_B) + ((size_t)c * NN + rowb) * 128 + j * 16;
            CPASYNC16(dst, src);
        }
    };

    auto compute = [&](int buf) {
        const uint32_t ab = sb + buf * BUFSZ;
#pragma unroll
        for (int g = 0; g < 4; g++) {
            uint32_t ah[8];
            LDSM4(ah[0], ah[1], ah[2], ah[3], ab + invA + g * 32);
            LDSM4(ah[4], ah[5], ah[6], ah[7], ab + invA + 16 * ASTRIDE + g * 32);
#pragma unroll
            for (int ng = 0; ng < 6; ng++) {
                uint32_t bf[4];
                LDSM4(bf[0], bf[1], bf[2], bf[3], ab + OFF_B + invB + ng * (16 * ASTRIDE) + g * 32);
#pragma unroll
                for (int mt = 0; mt < 2; mt++) {
                    mma16816(acc[mt][ng * 2 + 0], ah + mt * 4, bf + 0);
                    mma16816(acc[mt][ng * 2 + 1], ah + mt * 4, bf + 2);
                }
            }
        }
    };

    // ---- prologue ----
    loadA(0);
    loadB(0, 0);
    CPCOMMIT();
    stsA(0);
    CPWAIT0();
    __syncthreads();

    // ---- main loop ----
    for (int c = 0; c < NST; c++) {
        const int buf = c & 1;
        if (c < NST - 1) { loadA(c + 1); loadB(c + 1, buf ^ 1); CPCOMMIT(); }
        compute(buf);
        if (c < NST - 1) { stsA(buf ^ 1); CPWAIT0(); }
        __syncthreads();
    }

    // ---- write D ----
    const int l4 = lane >> 2;
    const int l2 = (lane & 3) * 2;
#pragma unroll
    for (int mt = 0; mt < 2; mt++) {
        const int mrow = blockIdx.x * MTILE + warpM + mt * 16 + l4;
        float* dbase = g_D + (size_t)mrow * NN + warpN + l2;
#pragma unroll
        for (int nt = 0; nt < 12; nt++) {
            *reinterpret_cast<float2*>(dbase + nt * 8)          = make_float2(acc[mt][nt][0], acc[mt][nt][1]);
            *reinterpret_cast<float2*>(dbase + nt * 8 + 8 * NN) = make_float2(acc[mt][nt][2], acc[mt][nt][3]);
        }
    }
}

// ---------------- kernel 2: combine + bias + relu + 1x1 conv + relu ----------------
__global__ void epilogue_kernel(const float* __restrict__ conv_b,
                                const float* __restrict__ conv2_w,
                                const float* __restrict__ conv2_b) {
    int gw   = (blockIdx.x * blockDim.x + threadIdx.x) >> 5;
    int lane = threadIdx.x & 31;
    if (gw >= BB * CC * TT) return;
    int b   = gw / (CC * TT);
    int rem = gw - b * (CC * TT);
    int c   = rem / TT;
    int t   = rem - c * TT;

    float sum = 0.0f;
#pragma unroll
    for (int kh = 0; kh < 3; kh++) {
#pragma unroll
        for (int h = 0; h < 2; h++) {
            size_t row = ((size_t)(b * RR + (c + kh)) * SS + (t + h));
            sum += g_D[row * NN + (kh * 2 + h) * 32 + lane];
        }
    }
    float y = fmaxf(sum + conv_b[lane], 0.0f);
    float v = y * conv2_w[lane];
#pragma unroll
    for (int o = 16; o > 0; o >>= 1)
        v += __shfl_xor_sync(0xffffffffu, v, o);
    if (lane == 0) {
        g_z[(b * CC + c) * TT + t] = fmaxf(v + conv2_b[0], 0.0f);
    }
}

// ---------------- kernel 3: RNN scan + sigmoid, smem-staged ----------------
#define RNN_LANES 64
__global__ __launch_bounds__(RNN_LANES) void rnn_kernel(
        const float* __restrict__ w_ih, const float* __restrict__ w_hh,
        const float* __restrict__ b_ih, const float* __restrict__ b_hh,
        const float* __restrict__ h0,   float* __restrict__ out) {
    __shared__ float zs[RNN_LANES * TT];
    const int tid = threadIdx.x;
    const int i0  = blockIdx.x * RNN_LANES;

    // coalesced stage of this block's 64 lanes (contiguous region of g_z)
    const float* src = g_z + (size_t)i0 * TT;
#pragma unroll 4
    for (int u = tid; u < RNN_LANES * TT; u += RNN_LANES) zs[u] = src[u];
    __syncthreads();

    const int i = i0 + tid;
    const float wih  = w_ih[0];
    const float whh  = w_hh[0];
    const float bias = b_ih[0] + b_hh[0];
    float h = h0[i / CC];
    const float* zp = zs + tid * TT;
#pragma unroll 3
    for (int t = 0; t < TT; t++) {
        float a = fmaf(wih, zp[t], fmaf(whh, h, bias));
        float e = __expf(2.0f * a);
        h = 1.0f - __fdividef(2.0f, e + 1.0f);   // tanh(a)
    }
    out[i] = __fdividef(1.0f, 1.0f + __expf(-h));
}

// ---------------- launcher ----------------
extern "C" void kernel_launch(void* const* d_in, const int* in_sizes, int n_in,
                              void* d_out, int out_size) {
    const float* x       = (const float*)d_in[0];
    const float* conv_w  = (const float*)d_in[1];
    const float* conv_b  = (const float*)d_in[2];
    const float* conv2_w = (const float*)d_in[3];
    const float* conv2_b = (const float*)d_in[4];
    const float* w_ih    = (const float*)d_in[5];
    const float* w_hh    = (const float*)d_in[6];
    const float* b_ih    = (const float*)d_in[7];
    const float* b_hh    = (const float*)d_in[8];
    const float* h0      = (const float*)d_in[9];
    float* out = (float*)d_out;

    static int smem_set = 0;
    if (!smem_set) {
        cudaFuncSetAttribute(seg_gemm_mma, cudaFuncAttributeMaxDynamicSharedMemorySize, SMEM_BYTES);
        smem_set = 1;
    }

    pack_w_kernel<<<(NST * NN * BK + 255) / 256, 256>>>(conv_w);

    seg_gemm_mma<<<(BB * RR * SS) / MTILE, 256, SMEM_BYTES>>>(x);   // 825 CTAs

    int total_warps = BB * CC * TT;
    epilogue_kernel<<<(total_warps * 32 + 255) / 256, 256>>>(conv_b, conv2_w, conv2_b);

    rnn_kernel<<<(BB * CC) / RNN_LANES, RNN_LANES>>>(w_ih, w_hh, b_ih, b_hh, h0, out);
}